// round 17
// baseline (speedup 1.0000x reference)
#include <cuda_runtime.h>
#include <cuda_bf16.h>
#include <cuda_fp16.h>
#include <math.h>
#include <stdint.h>

// Problem dims
#define Bz 32
#define Sz 128
#define Ez 512
#define Hz 1024
#define Gz 4096   // 4*H
#define Lz 128
#define Vz 32000
#define TDz 126   // S-2
#define NBLK 128  // persistent grid size

// ---------------- scratch (device globals; no runtime allocation) ----------------
__device__ float g_Pe[(size_t)Sz * Bz * Gz];
__device__ float g_Pd[(size_t)4096 * Gz];            // padded to 4096 rows
__device__ unsigned g_bars[8 * 64];                  // 8 counters, 256B stride (distinct LTS slices)
// fp16 state + weights
__device__ __half g_Ahe[(Sz + 1) * Bz * Hz];         // encoder h (slot 0 = zeros, BSS)
__device__ __half g_Ahd[4160 * Hz];                  // decoder h; slot0=hd0; tail rows stay zero
__device__ __half g_Wh[(size_t)Vz * Hz];
__device__ __half g_Xeh[4096 * Ez];
__device__ __half g_Xdh[4096 * Ez];                  // rows >= 4032 stay zero (BSS)
__device__ __half g_Wieh[Gz * Ez];
__device__ __half g_Widh[Gz * Ez];
__device__ __half g_WhheH[(size_t)Gz * Hz];
__device__ __half g_WhhdH[(size_t)Gz * Hz];

// ---------------- helpers ----------------
__device__ __forceinline__ float sigm(float x) { return 1.0f / (1.0f + expf(-x)); }

__device__ __forceinline__ uint32_t smem_u32(const void* p) {
    uint32_t a;
    asm("{ .reg .u64 t; cvta.to.shared.u64 t, %1; cvt.u32.u64 %0, t; }" : "=r"(a) : "l"(p));
    return a;
}

#define LDSM4(d, addr) \
    asm volatile("ldmatrix.sync.aligned.m8n8.x4.shared.b16 {%0,%1,%2,%3}, [%4];" \
        : "=r"((d)[0]), "=r"((d)[1]), "=r"((d)[2]), "=r"((d)[3]) : "r"(addr))
#define LDSM2(d, addr) \
    asm volatile("ldmatrix.sync.aligned.m8n8.x2.shared.b16 {%0,%1}, [%2];" \
        : "=r"((d)[0]), "=r"((d)[1]) : "r"(addr))

#define MMAH16816(c, a, b) \
    asm volatile("mma.sync.aligned.m16n8k16.row.col.f32.f16.f16.f32 " \
        "{%0,%1,%2,%3}, {%4,%5,%6,%7}, {%8,%9}, {%0,%1,%2,%3};" \
        : "+f"((c)[0]), "+f"((c)[1]), "+f"((c)[2]), "+f"((c)[3]) \
        : "r"((a)[0]), "r"((a)[1]), "r"((a)[2]), "r"((a)[3]), "r"((b)[0]), "r"((b)[1]))

#define CP_ASYNC16(smaddr, gptr) \
    asm volatile("cp.async.cg.shared.global [%0], [%1], 16;" :: "r"(smaddr), "l"(gptr))
#define CP_COMMIT() asm volatile("cp.async.commit_group;" ::: "memory")
#define CP_WAIT0()  asm volatile("cp.async.wait_group 0;" ::: "memory")

// ---------------- grid barrier (8-way split counters) ----------------
__device__ __forceinline__ void grid_sync_(unsigned target_total, int bid) {
    __syncthreads();
    if (threadIdx.x == 0) {
        __threadfence();
        atomicAdd(&g_bars[(bid & 7) * 64], 1u);
        unsigned total;
        do {
            total = 0;
#pragma unroll
            for (int i = 0; i < 8; i++) {
                unsigned v;
                asm volatile("ld.global.acquire.gpu.u32 %0, [%1];"
                             : "=r"(v) : "l"(&g_bars[i * 64]));
                total += v;
            }
        } while (total < target_total);
    }
    __syncthreads();
}

// ---------------- init (barrier reset only) ----------------
__global__ void init_kernel() {
    if (threadIdx.x < 8) g_bars[threadIdx.x * 64] = 0u;
}

// ---------------- embedding gather -> fp16 ----------------
__global__ void embed_h_kernel(const int* __restrict__ tokens, const float* __restrict__ emb,
                               __half* __restrict__ hi, int T, int toff) {
    int total4 = T * Bz * (Ez / 4);
    int i = blockIdx.x * blockDim.x + threadIdx.x;
    int stride = gridDim.x * blockDim.x;
    const int E4 = Ez / 4;
    for (; i < total4; i += stride) {
        int e4 = i % E4;
        int r  = i / E4;
        int b  = r % Bz;
        int t  = r / Bz;
        int tok = tokens[b * Sz + t + toff];
        float4 v = ((const float4*)(emb + (size_t)tok * Ez))[e4];
        __half2 a; a.x = __float2half_rn(v.x); a.y = __float2half_rn(v.y);
        __half2 b2; b2.x = __float2half_rn(v.z); b2.y = __float2half_rn(v.w);
        uint2 o;
        o.x = *(unsigned*)&a;
        o.y = *(unsigned*)&b2;
        ((uint2*)hi)[i] = o;
    }
}

// ---------------- fp16 convert (STG.64 stores) ----------------
__global__ void convert_w_kernel(const float* __restrict__ W, __half* __restrict__ out, int n4) {
    int i = blockIdx.x * blockDim.x + threadIdx.x;
    int stride = gridDim.x * blockDim.x;
    for (; i < n4; i += stride) {
        float4 v = ((const float4*)W)[i];
        __half2 a; a.x = __float2half_rn(v.x); a.y = __float2half_rn(v.y);
        __half2 b; b.x = __float2half_rn(v.z); b.y = __float2half_rn(v.w);
        uint2 o;
        o.x = *(unsigned*)&a;
        o.y = *(unsigned*)&b;
        ((uint2*)out)[i] = o;
    }
}

// ---------------- fp16 single-term mma GEMM (proj + logits) ----------------
#define SSTR   80
#define SA_1   0
#define SB_1   10240
#define STAGE1 20480
#define SBIAS1 (2 * STAGE1)
#define SMEM_MMA1 (2 * STAGE1 + 512)

// MODE 0: logits — out[(b*TD+t)*Nout + n] = acc + bias1[n], guard m < TDz*Bz
// MODE 1: proj   — out[m*Nout + n] = acc + bias1[n] + bias2[n]
template <int KDIM, int MODE>
__global__ __launch_bounds__(256, 2)
void mma1_kernel(const __half* __restrict__ Ah, const __half* __restrict__ Wh,
                 const float* __restrict__ bias1, const float* __restrict__ bias2,
                 float* __restrict__ out, int Nout) {
    extern __shared__ char smem[];
    const uint32_t sbase = smem_u32(smem);
    const int tid = threadIdx.x;
    const int w = tid >> 5, lane = tid & 31;
    const int mtile = blockIdx.x;
    const int ntile = blockIdx.y;
    const int wm = (w & 1) * 64;
    const int wn = (w >> 1) * 32;

    if (tid < 128) {
        float bv = bias1[ntile * 128 + tid];
        if (MODE == 1) bv += bias2[ntile * 128 + tid];
        ((float*)(smem + SBIAS1))[tid] = bv;
    }

    const int row = tid >> 2;
    const int ko  = (tid & 3) * 8;
    const __half* gA0 = Ah + (size_t)(mtile * 128 + row) * KDIM + ko;
    const __half* gA1 = Ah + (size_t)(mtile * 128 + row + 64) * KDIM + ko;
    const __half* gB0 = Wh + (size_t)(ntile * 128 + row) * KDIM + ko;
    const __half* gB1 = Wh + (size_t)(ntile * 128 + row + 64) * KDIM + ko;
    const uint32_t s0 = sbase + row * SSTR + ko * 2;
    const uint32_t s1 = sbase + (row + 64) * SSTR + ko * 2;

    const uint32_t aLane = sbase + (uint32_t)(wm + (lane & 15)) * SSTR + (uint32_t)(lane >> 4) * 16;
    const uint32_t bLane = sbase + (uint32_t)(wn + (lane & 7) + ((lane >> 4) << 3)) * SSTR +
                           (uint32_t)((lane >> 3) & 1) * 16;

    float acc[4][4][4];
#pragma unroll
    for (int i = 0; i < 4; i++)
#pragma unroll
        for (int j = 0; j < 4; j++)
#pragma unroll
            for (int q = 0; q < 4; q++) acc[i][j][q] = 0.f;

    CP_ASYNC16(s0 + SA_1, gA0); CP_ASYNC16(s1 + SA_1, gA1);
    CP_ASYNC16(s0 + SB_1, gB0); CP_ASYNC16(s1 + SB_1, gB1);
    CP_COMMIT();
    CP_WAIT0();
    __syncthreads();

    const int NT = KDIM / 32;
    for (int kt = 0; kt < NT; kt++) {
        const uint32_t stg = (uint32_t)(kt & 1) * STAGE1;

        if (kt < NT - 1) {
            const uint32_t nstg = (uint32_t)((kt + 1) & 1) * STAGE1;
            const int go = (kt + 1) * 32;
            CP_ASYNC16(s0 + nstg + SA_1, gA0 + go); CP_ASYNC16(s1 + nstg + SA_1, gA1 + go);
            CP_ASYNC16(s0 + nstg + SB_1, gB0 + go); CP_ASYNC16(s1 + nstg + SB_1, gB1 + go);
            CP_COMMIT();
        }

#pragma unroll
        for (int ks = 0; ks < 2; ks++) {
            const uint32_t kofs = (uint32_t)ks * 32;
            uint32_t bH[4][2];
#pragma unroll
            for (int nb2 = 0; nb2 < 2; nb2++) {
                uint32_t bd = stg + bLane + (uint32_t)nb2 * (16 * SSTR) + kofs;
                uint32_t t4[4];
                LDSM4(t4, bd + SB_1);
                bH[nb2 * 2][0] = t4[0]; bH[nb2 * 2][1] = t4[1];
                bH[nb2 * 2 + 1][0] = t4[2]; bH[nb2 * 2 + 1][1] = t4[3];
            }
#pragma unroll
            for (int ma = 0; ma < 4; ma++) {
                uint32_t ad = stg + aLane + (uint32_t)ma * (16 * SSTR) + kofs;
                uint32_t aH[4];
                LDSM4(aH, ad + SA_1);
#pragma unroll
                for (int nb = 0; nb < 4; nb++) {
                    MMAH16816(acc[ma][nb], aH, bH[nb]);
                }
            }
        }

        CP_WAIT0();
        __syncthreads();
    }

    const float* sb = (const float*)(smem + SBIAS1);
#pragma unroll
    for (int ma = 0; ma < 4; ma++) {
        const int m0 = mtile * 128 + wm + ma * 16 + (lane >> 2);
#pragma unroll
        for (int nb = 0; nb < 4; nb++) {
            const int cl = wn + nb * 8 + (lane & 3) * 2;
            const float b0v = sb[cl], b1v = sb[cl + 1];
            const size_t col = (size_t)(ntile * 128 + cl);
            if (MODE == 0) {
                if (m0 < TDz * Bz) {
                    int orow = (m0 & 31) * TDz + (m0 >> 5);
                    float2 v;
                    v.x = acc[ma][nb][0] + b0v;
                    v.y = acc[ma][nb][1] + b1v;
                    *(float2*)(out + (size_t)orow * Nout + col) = v;
                }
                const int m1 = m0 + 8;
                if (m1 < TDz * Bz) {
                    int orow = (m1 & 31) * TDz + (m1 >> 5);
                    float2 v;
                    v.x = acc[ma][nb][2] + b0v;
                    v.y = acc[ma][nb][3] + b1v;
                    *(float2*)(out + (size_t)orow * Nout + col) = v;
                }
            } else {
                float2 v;
                v.x = acc[ma][nb][0] + b0v;
                v.y = acc[ma][nb][1] + b1v;
                *(float2*)(out + (size_t)m0 * Nout + col) = v;
                v.x = acc[ma][nb][2] + b0v;
                v.y = acc[ma][nb][3] + b1v;
                *(float2*)(out + (size_t)(m0 + 8) * Nout + col) = v;
            }
        }
    }
}

// ---------------- persistent LSTM: HMMA recurrence, single-fp16 smem weights ----------------
// smem layout (bytes); rows 2064B-strided (2048 data + 16 pad -> conflict-free ldmatrix)
#define ROWB   2064
#define SW     0
#define SH     66048
#define SGT    132096                 // float gates [32][33]
#define SPF    136320                 // float P [32*33]
#define SLAT   140544                 // latent scratch
#define SMEM_LSTM (140544 + 2048 + 1536 + 64)

__device__ __forceinline__ void load_whh_smem(const __half* __restrict__ WH,
                                              char* smp, int u0, int w, int lane) {
#pragma unroll
    for (int rr = 0; rr < 2; rr++) {
        int n = w + rr * 16;                       // smem row 0..31
        size_t grow = ((size_t)(n >> 3) * Hz + u0 + (n & 7)) * Hz;
#pragma unroll
        for (int j = 0; j < 4; j++) {
            *(uint4*)(smp + SW + n * ROWB + j * 512 + lane * 16) =
                *(const uint4*)(WH + grow + j * 256 + lane * 8);
        }
    }
}

// one LSTM step. gates = h @ Whh^T via HMMA; c fp32 in registers; h emitted fp16.
__device__ __forceinline__ float lstm_step_mma(
    char* smp, uint32_t sbase,
    const float* __restrict__ P, const __half* __restrict__ hin,
    __half* __restrict__ hout, float creg,
    int u0, int tid, int w, int lane)
{
    // 1) cp.async h tile (32 x 1024 fp16) into smem
    {
#pragma unroll
        for (int rr = 0; rr < 2; rr++) {
            int n = w + rr * 16;
#pragma unroll
            for (int j = 0; j < 4; j++) {
                CP_ASYNC16(sbase + SH + n * ROWB + j * 512 + lane * 16,
                           hin + (size_t)n * Hz + j * 256 + lane * 8);
            }
        }
        CP_COMMIT();
    }
    // 2) P prefetch
    {
        float* sPf = (float*)(smp + SPF);
#pragma unroll
        for (int k = 0; k < 2; k++) {
            int idx = tid + k * 512;
            int b = idx >> 5, c = idx & 31;
            sPf[b * 33 + c] = P[(size_t)b * Gz + (c >> 3) * Hz + u0 + (c & 7)];
        }
    }
    CP_WAIT0();
    __syncthreads();

    // 3) HMMA: warp -> (m-tile, n-tile, k-half)
    const int combo = w >> 1;
    const int mt = combo >> 2;       // 0..1
    const int nt = combo & 3;        // 0..3  (= gate index)
    const int kh = w & 1;

    float c4[4] = {0.f, 0.f, 0.f, 0.f};
    const uint32_t aBase = sbase + SH + (uint32_t)(mt * 16 + (lane & 15)) * ROWB +
                           (uint32_t)(lane >> 4) * 16;
    const uint32_t bRow = (uint32_t)(nt * 8 + (lane & 7)) * ROWB +
                          (uint32_t)((lane >> 3) & 1) * 16;

#pragma unroll 4
    for (int kt = kh * 32; kt < kh * 32 + 32; kt++) {
        const uint32_t ka = (uint32_t)kt * 32;
        uint32_t a[4];
        LDSM4(a, aBase + ka);
        uint32_t bh[2];
        LDSM2(bh, sbase + SW + bRow + ka);
        MMAH16816(c4, a, bh);
    }

    // 4) k-half reduction via gates smem
    float* gt = (float*)(smp + SGT);
    const int mrow = mt * 16 + (lane >> 2);
    const int ncol = nt * 8 + (lane & 3) * 2;
    if (kh == 1) {
        gt[mrow * 33 + ncol]           = c4[0];
        gt[mrow * 33 + ncol + 1]       = c4[1];
        gt[(mrow + 8) * 33 + ncol]     = c4[2];
        gt[(mrow + 8) * 33 + ncol + 1] = c4[3];
    }
    __syncthreads();
    if (kh == 0) {
        gt[mrow * 33 + ncol]           += c4[0];
        gt[mrow * 33 + ncol + 1]       += c4[1];
        gt[(mrow + 8) * 33 + ncol]     += c4[2];
        gt[(mrow + 8) * 33 + ncol + 1] += c4[3];
    }
    __syncthreads();

    // 5) epilogue: tid<256 -> (ul = tid&7, b = tid>>3)
    float newc = creg;
    if (tid < 256) {
        const float* sPf = (const float*)(smp + SPF);
        int ul = tid & 7, b = tid >> 3;
        float gi = gt[b * 33 +  0 + ul] + sPf[b * 33 +  0 + ul];
        float gf = gt[b * 33 +  8 + ul] + sPf[b * 33 +  8 + ul];
        float gg = gt[b * 33 + 16 + ul] + sPf[b * 33 + 16 + ul];
        float go = gt[b * 33 + 24 + ul] + sPf[b * 33 + 24 + ul];
        float cc = sigm(gf) * creg + sigm(gi) * tanhf(gg);
        float hh = sigm(go) * tanhf(cc);
        hout[b * Hz + u0 + ul] = __float2half_rn(hh);
        newc = cc;
    }
    return newc;
}

// latent head (fp16 h input), 512 threads
__device__ void latent_dev(int b, int tid, char* smp,
                           const int* __restrict__ tokens, const __half* __restrict__ hs,
                           const float* __restrict__ Wmu, const float* __restrict__ bmu,
                           const float* __restrict__ Wlv, const float* __restrict__ blv,
                           const float* __restrict__ eps,
                           const float* __restrict__ Wl2h, const float* __restrict__ bl2h,
                           float* __restrict__ out_mean, float* __restrict__ out_lv,
                           __half* __restrict__ hd0) {
    int* scnt    = (int*)(smp + SLAT);
    float* smean = (float*)(smp + SLAT + 2048);
    float* slv   = smean + 128;
    float* szv   = slv + 128;

    int cnt = 0;
    if (tid < Sz) cnt = (tokens[b * Sz + tid] != 0) ? 1 : 0;
    scnt[tid] = cnt;
    __syncthreads();
    for (int off = 256; off >= 1; off >>= 1) {
        if (tid < off) scnt[tid] += scnt[tid + off];
        __syncthreads();
    }
    int last = scnt[0] - 1;
    if (last < 0) last = 0;

    const __half* lh = hs + (size_t)(last + 1) * Bz * Hz + (size_t)b * Hz;
    if (tid < 256) {
        int j = tid & 127;
        const float* Wr = ((tid < 128) ? Wmu : Wlv) + (size_t)j * Hz;
        float acc = 0.f;
        const __half2* l2 = (const __half2*)lh;
        const float2* w2 = (const float2*)Wr;
#pragma unroll 4
        for (int k = 0; k < Hz / 2; k++) {
            float2 a = __half22float2(l2[k]);
            float2 ww = w2[k];
            acc += a.x * ww.x + a.y * ww.y;
        }
        if (tid < 128) smean[j] = acc + bmu[j];
        else           slv[j]   = acc + blv[j];
    }
    __syncthreads();

    if (tid < 128) {
        float m = smean[tid];
        float lv = slv[tid];
        out_mean[b * Lz + tid] = m;
        out_lv[b * Lz + tid] = lv;
        szv[tid] = m + eps[b * Lz + tid] * expf(0.5f * lv);
    }
    __syncthreads();

#pragma unroll
    for (int r = 0; r < 2; r++) {
        int u = tid + r * 512;
        float acc = bl2h[u];
        const float* wr = Wl2h + (size_t)u * Lz;
#pragma unroll 4
        for (int l = 0; l < Lz; l++) acc += szv[l] * wr[l];
        hd0[b * Hz + u] = __float2half_rn(acc);
    }
}

__global__ __launch_bounds__(512, 1)
void lstm_persistent(const __half* __restrict__ WeH, const __half* __restrict__ WdH,
                     const float* __restrict__ Pe, const float* __restrict__ Pd,
                     __half* __restrict__ Ahe, __half* __restrict__ Ahd,
                     const int* __restrict__ tokens,
                     const float* __restrict__ Wmu, const float* __restrict__ bmu,
                     const float* __restrict__ Wlv, const float* __restrict__ blv,
                     const float* __restrict__ eps,
                     const float* __restrict__ Wl2h, const float* __restrict__ bl2h,
                     float* __restrict__ out_mean, float* __restrict__ out_lv) {
    extern __shared__ char smp[];
    const uint32_t sbase = smem_u32(smp);
    const int tid = threadIdx.x;
    const int w = tid >> 5;
    const int lane = tid & 31;
    const int bid = blockIdx.x;
    const int u0 = bid * 8;

    load_whh_smem(WeH, smp, u0, w, lane);
    __syncthreads();

    float creg = 0.f;
    unsigned epoch = 0;

    for (int t = 0; t < Sz; t++) {
        creg = lstm_step_mma(smp, sbase, Pe + (size_t)t * Bz * Gz,
                             Ahe + (size_t)t * Bz * Hz,
                             Ahe + (size_t)(t + 1) * Bz * Hz,
                             creg, u0, tid, w, lane);
        epoch++;
        grid_sync_(epoch * NBLK, bid);
    }

    load_whh_smem(WdH, smp, u0, w, lane);
    if (bid < 32) {
        latent_dev(bid, tid, smp, tokens, Ahe, Wmu, bmu, Wlv, blv, eps,
                   Wl2h, bl2h, out_mean, out_lv, Ahd);
    }
    epoch++;
    grid_sync_(epoch * NBLK, bid);

    creg = 0.f;
    for (int t = 0; t < TDz; t++) {
        creg = lstm_step_mma(smp, sbase, Pd + (size_t)t * Bz * Gz,
                             Ahd + (size_t)t * Bz * Hz,
                             Ahd + (size_t)(t + 1) * Bz * Hz,
                             creg, u0, tid, w, lane);
        if (t < TDz - 1) {
            epoch++;
            grid_sync_(epoch * NBLK, bid);
        }
    }
}

// ---------------- launch ----------------
extern "C" void kernel_launch(void* const* d_in, const int* in_sizes, int n_in,
                              void* d_out, int out_size) {
    const int*   tokens  = (const int*)d_in[0];
    const float* emb_enc = (const float*)d_in[1];
    const float* Wih_e   = (const float*)d_in[2];
    const float* Whh_e   = (const float*)d_in[3];
    const float* bih_e   = (const float*)d_in[4];
    const float* bhh_e   = (const float*)d_in[5];
    const float* W_mu    = (const float*)d_in[6];
    const float* b_mu    = (const float*)d_in[7];
    const float* W_lv    = (const float*)d_in[8];
    const float* b_lv    = (const float*)d_in[9];
    const float* emb_dec = (const float*)d_in[10];
    const float* W_l2h   = (const float*)d_in[11];
    const float* b_l2h   = (const float*)d_in[12];
    const float* Wih_d   = (const float*)d_in[13];
    const float* Whh_d   = (const float*)d_in[14];
    const float* bih_d   = (const float*)d_in[15];
    const float* bhh_d   = (const float*)d_in[16];
    const float* W_out   = (const float*)d_in[17];
    const float* b_out   = (const float*)d_in[18];
    const float* epsv    = (const float*)d_in[19];

    float* out = (float*)d_out;
    const size_t LOGITS = (size_t)Bz * TDz * Vz;
    float* out_logits = out;
    float* out_mean   = out + LOGITS;
    float* out_lv     = out + LOGITS + (size_t)Bz * Lz;

    float *p_Pe, *p_Pd;
    __half *p_Wh, *p_Ahe, *p_Ahd;
    __half *p_Xeh, *p_Xdh;
    __half *p_Wieh, *p_Widh;
    __half *p_WeH, *p_WdH;
    cudaGetSymbolAddress((void**)&p_Pe,  g_Pe);
    cudaGetSymbolAddress((void**)&p_Pd,  g_Pd);
    cudaGetSymbolAddress((void**)&p_Wh,  g_Wh);
    cudaGetSymbolAddress((void**)&p_Ahe, g_Ahe);
    cudaGetSymbolAddress((void**)&p_Ahd, g_Ahd);
    cudaGetSymbolAddress((void**)&p_Xeh, g_Xeh);
    cudaGetSymbolAddress((void**)&p_Xdh, g_Xdh);
    cudaGetSymbolAddress((void**)&p_Wieh, g_Wieh);
    cudaGetSymbolAddress((void**)&p_Widh, g_Widh);
    cudaGetSymbolAddress((void**)&p_WeH, g_WhheH);
    cudaGetSymbolAddress((void**)&p_WdH, g_WhhdH);

    cudaFuncSetAttribute(mma1_kernel<512, 1>, cudaFuncAttributeMaxDynamicSharedMemorySize, SMEM_MMA1);
    cudaFuncSetAttribute(mma1_kernel<1024, 0>, cudaFuncAttributeMaxDynamicSharedMemorySize, SMEM_MMA1);
    cudaFuncSetAttribute(lstm_persistent, cudaFuncAttributeMaxDynamicSharedMemorySize, SMEM_LSTM);

    // 1) reset grid barrier counters
    init_kernel<<<1, 32>>>();

    // 2) embeddings -> fp16
    embed_h_kernel<<<1024, 256>>>(tokens, emb_enc, p_Xeh, Sz, 0);
    embed_h_kernel<<<1024, 256>>>(tokens, emb_dec, p_Xdh, TDz, 1);

    // 2b) weight converts (all single fp16, STG.64 stores)
    convert_w_kernel<<<1024, 256>>>(Wih_e, p_Wieh, Gz * Ez / 4);
    convert_w_kernel<<<1024, 256>>>(Wih_d, p_Widh, Gz * Ez / 4);
    convert_w_kernel<<<1024, 256>>>(Whh_e, p_WeH, Gz * Hz / 4);
    convert_w_kernel<<<1024, 256>>>(Whh_d, p_WdH, Gz * Hz / 4);

    // 3) input projections via single-term fp16 mma (K=512)
    {
        dim3 grid(32, 32);
        mma1_kernel<512, 1><<<grid, 256, SMEM_MMA1>>>(p_Xeh, p_Wieh,
                                                      bih_e, bhh_e, p_Pe, Gz);
        mma1_kernel<512, 1><<<grid, 256, SMEM_MMA1>>>(p_Xdh, p_Widh,
                                                      bih_d, bhh_d, p_Pd, Gz);
    }

    // 3b) W_out fp16 convert
    convert_w_kernel<<<4096, 256>>>(W_out, p_Wh, (int)((size_t)Vz * Hz / 4));

    // 4+5+6) recurrences (HMMA, single-fp16 weights) + latent head
    lstm_persistent<<<NBLK, 512, SMEM_LSTM>>>(p_WeH, p_WdH,
                                              p_Pe, p_Pd, p_Ahe, p_Ahd,
                                              tokens, W_mu, b_mu, W_lv, b_lv, epsv,
                                              W_l2h, b_l2h, out_mean, out_lv);

    // 7) logits via single-term fp16 mma (K=1024); A = decoder h slots 1..126
    {
        dim3 grid(32, 250);
        mma1_kernel<1024, 0><<<grid, 256, SMEM_MMA1>>>(p_Ahd + (size_t)Bz * Hz, p_Wh,
                                                       b_out, b_out, out_logits, Vz);
    }
}